// round 17
// baseline (speedup 1.0000x reference)
#include <cuda_runtime.h>

// AudioLSTM: 2-layer LSTM (26 -> 64 -> 32) over T=1000, B=512, + FC 32->16->10.
// Round 17: warp-shuffle reduce-scatter across the 8 K-splits of each unit
// (same 8 lanes) -> no smem exchange, no updater phase, ONE bar.sync per step.
// h1/h2 double-buffered (read [t&1], write [(t+1)&1]). Owner lane s<4 of each
// 8-lane group updates batch s. 768 threads, weights register-resident.

#define IN   26
#define H1   64
#define H2   32
#define NB   512
#define TT   1000
#define BPC  4
#define NT   768
#define R1   68     // sh1 row stride (16B-aligned, bank skew 4/batch)
#define R2   36     // sh2 row stride

typedef unsigned long long ull;

__device__ __forceinline__ ull pack2(float lo, float hi) {
    ull r;
    asm("mov.b64 %0, {%1, %2};" : "=l"(r) : "f"(lo), "f"(hi));
    return r;
}
__device__ __forceinline__ float sum2(ull a) {
    float lo, hi;
    asm("mov.b64 {%0, %1}, %2;" : "=f"(lo), "=f"(hi) : "l"(a));
    return lo + hi;
}
__device__ __forceinline__ ull fma2(ull a, ull b, ull c) {
    ull d;
    asm("fma.rn.f32x2 %0, %1, %2, %3;" : "=l"(d) : "l"(a), "l"(b), "l"(c));
    return d;
}

#define BAR() asm volatile("bar.sync 0;" ::: "memory")
#define SHX(v, m) __shfl_xor_sync(0xffffffffu, (v), (m))

__device__ __forceinline__ float tanha(float x) {
    float y;
    asm("tanh.approx.f32 %0, %1;" : "=f"(y) : "f"(x));
    return y;
}
__device__ __forceinline__ float sigm(float x) {
    return __fmaf_rn(0.5f, tanha(0.5f * x), 0.5f);
}

__global__ void __launch_bounds__(NT, 1)
audiolstm_kernel(const float* __restrict__ x,
                 const float* __restrict__ w_ih1, const float* __restrict__ w_hh1,
                 const float* __restrict__ b_ih1, const float* __restrict__ b_hh1,
                 const float* __restrict__ w_ih2, const float* __restrict__ w_hh2,
                 const float* __restrict__ b_ih2, const float* __restrict__ b_hh2,
                 const float* __restrict__ w_fc1, const float* __restrict__ b_fc1,
                 const float* __restrict__ w_fc2, const float* __restrict__ b_fc2,
                 float* __restrict__ out)
{
    const int b0   = blockIdx.x * BPC;
    const int tid  = threadIdx.x;
    const int lane = tid & 31;

    __shared__ __align__(16) float sh1[2][BPC][R1];   // h1 double buffer
    __shared__ __align__(16) float sh2[2][BPC][R2];   // h2 double buffer
    __shared__ __align__(16) float sx[BPC][2][32];    // x double buffer, 26..31 = 0
    __shared__ __align__(16) float sb1[4 * H1];
    __shared__ __align__(16) float sb2[4 * H2];
    __shared__ __align__(16) float sf[BPC][16];

    // ---- init (ordered by first BAR) ----
    if (tid < 256) sb1[tid] = b_ih1[tid] + b_hh1[tid];
    if (tid < 128) sb2[tid] = b_ih2[tid] + b_hh2[tid];
    if (tid < BPC * H1) sh1[0][tid >> 6][tid & 63] = 0.0f;
    if (tid < 2 * BPC * H2) {
        int q = tid;
        sh2[q >> 7][(q >> 5) & 3][q & 31] = 0.0f;
    }
    if (tid < BPC * 2 * 6) {   // zero x pads 26..31, both buffers, 4 batches
        int bb = tid / 12, rem = tid - bb * 12;
        sx[bb][rem / 6][26 + (rem % 6)] = 0.0f;
    }

    if (tid < 512) {
        // ================= Layer 1: unit u, K-eighth s, 4 gates x 4 batches =====
        const int s = lane & 7;
        const int u = (tid >> 5) * 4 + (lane >> 3);
        ull wh[4][4], wx[4][2];
        #pragma unroll
        for (int g = 0; g < 4; g++) {
            const int row = g * 64 + u;
            #pragma unroll
            for (int k = 0; k < 4; k++)
                wh[g][k] = pack2(w_hh1[row * H1 + s * 8 + 2 * k],
                                 w_hh1[row * H1 + s * 8 + 2 * k + 1]);
            #pragma unroll
            for (int k = 0; k < 2; k++) {
                int i0 = s * 4 + 2 * k, i1 = i0 + 1;
                wx[g][k] = pack2(i0 < IN ? w_ih1[row * IN + i0] : 0.0f,
                                 i1 < IN ? w_ih1[row * IN + i1] : 0.0f);
            }
        }
        const bool owner = (s < 4);     // owner lane s updates batch s of unit u
        float c1 = 0.0f;

        // loader role among s>=4 lanes: 256 candidates, 104 used
        const int  li      = (tid >> 5) * 16 + (lane >> 3) * 4 + (s - 4);
        const bool is_load = (s >= 4) && (li < BPC * IN);
        const int  lic     = is_load ? li : 0;
        const int  bbx     = lic / IN;
        const int  xi      = lic - bbx * IN;
        const size_t xbase = (size_t)(b0 + bbx) * (size_t)(IN * TT) + (size_t)xi * TT;
        float xreg = 0.0f;
        if (is_load) {
            sx[bbx][0][xi] = x[xbase + 0];
            xreg = x[xbase + 1];
        }

        #pragma unroll 1
        for (int t = 0; t <= TT; t++) {
            BAR();
            if (t < TT) {
                const int buf = t & 1, nb = 1 - buf;
                float val[4][4];
                #pragma unroll
                for (int bb = 0; bb < BPC; bb++) {
                    const ulonglong2* hp = (const ulonglong2*)&sh1[buf][bb][s * 8];
                    ulonglong2 ha = hp[0], hb = hp[1];
                    ulonglong2 xv = *(const ulonglong2*)&sx[bb][buf][s * 4];
                    #pragma unroll
                    for (int g = 0; g < 4; g++) {
                        ull a = fma2(ha.x, wh[g][0], 0ull);
                        a = fma2(ha.y, wh[g][1], a);
                        a = fma2(hb.x, wh[g][2], a);
                        a = fma2(hb.y, wh[g][3], a);
                        a = fma2(xv.x, wx[g][0], a);
                        a = fma2(xv.y, wx[g][1], a);
                        val[g][bb] = sum2(a);
                    }
                }
                // ---- reduce-scatter over 8 split-lanes ----
                // round 1 (xor 4): keep gate-pair (i,f) on s<4, (g,o) on s>=4
                float w0[4], w1[4];
                #pragma unroll
                for (int bb = 0; bb < 4; bb++) {
                    float r0 = SHX(val[0][bb], 4), r1 = SHX(val[1][bb], 4);
                    float r2 = SHX(val[2][bb], 4), r3 = SHX(val[3][bb], 4);
                    w0[bb] = owner ? val[0][bb] + r0 : val[2][bb] + r2;
                    w1[bb] = owner ? val[1][bb] + r1 : val[3][bb] + r3;
                }
                // round 2 (xor 2): keep batch-pair {0,1} on s&2==0 else {2,3}
                float p00 = SHX(w0[0], 2), p01 = SHX(w0[1], 2), p02 = SHX(w0[2], 2), p03 = SHX(w0[3], 2);
                float p10 = SHX(w1[0], 2), p11 = SHX(w1[1], 2), p12 = SHX(w1[2], 2), p13 = SHX(w1[3], 2);
                const bool lo2 = (s & 2) == 0;
                float u00 = lo2 ? w0[0] + p00 : w0[2] + p02;
                float u01 = lo2 ? w0[1] + p01 : w0[3] + p03;
                float u10 = lo2 ? w1[0] + p10 : w1[2] + p12;
                float u11 = lo2 ? w1[1] + p11 : w1[3] + p13;
                // round 3 (xor 1): keep one batch
                float q00 = SHX(u00, 1), q01 = SHX(u01, 1);
                float q10 = SHX(u10, 1), q11 = SHX(u11, 1);
                const bool lo1 = (s & 1) == 0;
                float z0 = lo1 ? u00 + q00 : u01 + q01;   // gate i (s<4) / g (s>=4)
                float z1 = lo1 ? u10 + q10 : u11 + q11;   // gate f (s<4) / o (s>=4)
                // gather (xor 4): owner gets (g,o) from its partner
                float y0 = SHX(z0, 4);
                float y1 = SHX(z1, 4);

                if (owner) {   // batch s
                    float ir  = z0 + sb1[u];
                    float fr  = z1 + sb1[64 + u];
                    float gr  = y0 + sb1[128 + u];
                    float orr = y1 + sb1[192 + u];
                    float ig = sigm(ir) * tanha(gr);
                    c1 = __fmaf_rn(sigm(fr), c1, ig);
                    sh1[nb][s][u] = sigm(orr) * tanha(c1);
                } else if (is_load && t + 1 < TT) {
                    sx[bbx][nb][xi] = xreg;
                    if (t + 2 < TT) xreg = x[xbase + (t + 2)];
                }
            }
        }
    } else {
        // ================= Layer 2: unit u2, K-eighth s; lags one step ==========
        const int s  = lane & 7;
        const int u2 = ((tid - 512) >> 5) * 4 + (lane >> 3);
        ull wi[4][4], wr[4][2];
        #pragma unroll
        for (int g = 0; g < 4; g++) {
            const int row = g * 32 + u2;
            #pragma unroll
            for (int k = 0; k < 4; k++)
                wi[g][k] = pack2(w_ih2[row * H1 + s * 8 + 2 * k],
                                 w_ih2[row * H1 + s * 8 + 2 * k + 1]);
            #pragma unroll
            for (int k = 0; k < 2; k++)
                wr[g][k] = pack2(w_hh2[row * H2 + s * 4 + 2 * k],
                                 w_hh2[row * H2 + s * 4 + 2 * k + 1]);
        }
        const bool owner = (s < 4);
        float c2 = 0.0f;

        #pragma unroll 1
        for (int t = 0; t <= TT; t++) {
            BAR();
            if (t > 0) {
                // step t-1: uses h1(t-1) = sh1[t&1], h2(t-2) = sh2[t&1]
                const int buf = t & 1, nb = 1 - buf;
                float val[4][4];
                #pragma unroll
                for (int bb = 0; bb < BPC; bb++) {
                    const ulonglong2* hp = (const ulonglong2*)&sh1[buf][bb][s * 8];
                    ulonglong2 ha = hp[0], hb = hp[1];
                    ulonglong2 hv = *(const ulonglong2*)&sh2[buf][bb][s * 4];
                    #pragma unroll
                    for (int g = 0; g < 4; g++) {
                        ull a = fma2(ha.x, wi[g][0], 0ull);
                        a = fma2(ha.y, wi[g][1], a);
                        a = fma2(hb.x, wi[g][2], a);
                        a = fma2(hb.y, wi[g][3], a);
                        a = fma2(hv.x, wr[g][0], a);
                        a = fma2(hv.y, wr[g][1], a);
                        val[g][bb] = sum2(a);
                    }
                }
                float w0[4], w1[4];
                #pragma unroll
                for (int bb = 0; bb < 4; bb++) {
                    float r0 = SHX(val[0][bb], 4), r1 = SHX(val[1][bb], 4);
                    float r2 = SHX(val[2][bb], 4), r3 = SHX(val[3][bb], 4);
                    w0[bb] = owner ? val[0][bb] + r0 : val[2][bb] + r2;
                    w1[bb] = owner ? val[1][bb] + r1 : val[3][bb] + r3;
                }
                float p00 = SHX(w0[0], 2), p01 = SHX(w0[1], 2), p02 = SHX(w0[2], 2), p03 = SHX(w0[3], 2);
                float p10 = SHX(w1[0], 2), p11 = SHX(w1[1], 2), p12 = SHX(w1[2], 2), p13 = SHX(w1[3], 2);
                const bool lo2 = (s & 2) == 0;
                float u00 = lo2 ? w0[0] + p00 : w0[2] + p02;
                float u01 = lo2 ? w0[1] + p01 : w0[3] + p03;
                float u10 = lo2 ? w1[0] + p10 : w1[2] + p12;
                float u11 = lo2 ? w1[1] + p11 : w1[3] + p13;
                float q00 = SHX(u00, 1), q01 = SHX(u01, 1);
                float q10 = SHX(u10, 1), q11 = SHX(u11, 1);
                const bool lo1 = (s & 1) == 0;
                float z0 = lo1 ? u00 + q00 : u01 + q01;
                float z1 = lo1 ? u10 + q10 : u11 + q11;
                float y0 = SHX(z0, 4);
                float y1 = SHX(z1, 4);

                if (owner) {
                    float ir  = z0 + sb2[u2];
                    float fr  = z1 + sb2[32 + u2];
                    float gr  = y0 + sb2[64 + u2];
                    float orr = y1 + sb2[96 + u2];
                    float ig = sigm(ir) * tanha(gr);
                    c2 = __fmaf_rn(sigm(fr), c2, ig);
                    sh2[nb][s][u2] = sigm(orr) * tanha(c2);
                }
            }
        }
    }

    // ---- FC head ----  final h2(T-1) is in sh2[(TT+1)&1] = sh2[1]
    BAR();
    if (tid < BPC * 16) {
        int fb = tid >> 4, fj = tid & 15;
        float acc = b_fc1[fj];
        #pragma unroll
        for (int k = 0; k < H2; k++)
            acc = __fmaf_rn(w_fc1[fj * H2 + k], sh2[(TT + 1) & 1][fb][k], acc);
        sf[fb][fj] = fmaxf(acc, 0.0f);
    }
    BAR();
    if (tid < BPC * 10) {
        int fb = tid / 10, fj = tid - fb * 10;
        float acc = b_fc2[fj];
        #pragma unroll
        for (int k = 0; k < 16; k++)
            acc = __fmaf_rn(w_fc2[fj * 16 + k], sf[fb][k], acc);
        out[(b0 + fb) * 10 + fj] = acc;
    }
}

extern "C" void kernel_launch(void* const* d_in, const int* in_sizes, int n_in,
                              void* d_out, int out_size)
{
    const float* x     = (const float*)d_in[0];
    const float* w_ih1 = (const float*)d_in[1];
    const float* w_hh1 = (const float*)d_in[2];
    const float* b_ih1 = (const float*)d_in[3];
    const float* b_hh1 = (const float*)d_in[4];
    const float* w_ih2 = (const float*)d_in[5];
    const float* w_hh2 = (const float*)d_in[6];
    const float* b_ih2 = (const float*)d_in[7];
    const float* b_hh2 = (const float*)d_in[8];
    const float* w_fc1 = (const float*)d_in[9];
    const float* b_fc1 = (const float*)d_in[10];
    const float* w_fc2 = (const float*)d_in[11];
    const float* b_fc2 = (const float*)d_in[12];
    float* out = (float*)d_out;

    audiolstm_kernel<<<NB / BPC, NT>>>(x, w_ih1, w_hh1, b_ih1, b_hh1,
                                       w_ih2, w_hh2, b_ih2, b_hh2,
                                       w_fc1, b_fc1, w_fc2, b_fc2, out);
}